// round 14
// baseline (speedup 1.0000x reference)
#include <cuda_runtime.h>
#include <cuda_fp16.h>
#include <math.h>
#include <string.h>

#define NN 50000
#define EE 1600000
#define DEG_SCALE 67108864.0f          /* 2^26 fixed-point for packed deg */
#define MB_TOTAL 391                   /* ceil(NN/128) */

// ---------------- scratch (static device arrays; no allocation) ----------------
static __device__ __align__(16) __half g_XH[(size_t)NN * 256];  // [N, X(128)|H(128)] fp16
static __device__ __align__(16) __half g_Gh[(size_t)NN * 256];  // [N,256] agg result, fp16
static __device__ __align__(16) __half g_Wh[512 * 256];  // W_cat^T: [n=512][k=256] fp16
static __device__ unsigned long long g_degcnt[NN];  // low40: deg fixed-point, high: cnt
static __device__ float g_dis[NN];
static __device__ unsigned g_slot[EE];           // per-edge slot within its dst row
static __device__ int   g_rowoff[NN + 1];
static __device__ uint2 g_edata[EE];             // (src, bitcast(norm)) CSR-permuted
static __device__ int   g_is64;                  // 1 if edge_index really is int64

// ---------------- small helpers ----------------
__device__ __forceinline__ float sigm(float x) { return 1.0f / (1.0f + expf(-x)); }

__device__ __forceinline__ unsigned h2_bits(__half2 h) {
    unsigned u;
    memcpy(&u, &h, sizeof(u));
    return u;
}

__device__ __forceinline__ int edge_src(const void* ei, int e, int is64) {
    if (is64) return (int)((const long long*)ei)[e];
    return ((const int*)ei)[e];
}
__device__ __forceinline__ int edge_dst(const void* ei, int e, int is64) {
    if (is64) return (int)((const long long*)ei)[(size_t)EE + e];
    return ((const int*)ei)[(size_t)EE + e];
}

// cp.async 16B with zero-fill when pred==0
__device__ __forceinline__ void cpa16(unsigned smem, const void* g, int pred) {
    asm volatile("cp.async.ca.shared.global [%0], [%1], 16, %2;"
                 :: "r"(smem), "l"(g), "r"(pred ? 16 : 0));
}

__device__ __forceinline__ void ldsm_x4(unsigned& r0, unsigned& r1, unsigned& r2,
                                        unsigned& r3, unsigned addr) {
    asm volatile("ldmatrix.sync.aligned.m8n8.x4.shared.b16 {%0,%1,%2,%3}, [%4];"
                 : "=r"(r0), "=r"(r1), "=r"(r2), "=r"(r3) : "r"(addr));
}
__device__ __forceinline__ void ldsm_x2(unsigned& r0, unsigned& r1, unsigned addr) {
    asm volatile("ldmatrix.sync.aligned.m8n8.x2.shared.b16 {%0,%1}, [%2];"
                 : "=r"(r0), "=r"(r1) : "r"(addr));
}

// ---------------- preprocessing kernels ----------------
__global__ void detect_kernel(const void* ei) {
    __shared__ int bad;
    if (threadIdx.x == 0) bad = 0;
    __syncthreads();
    long long v = ((const long long*)ei)[threadIdx.x];
    if (v < 0 || v >= NN) bad = 1;   // benign race, any writer sets 1
    __syncthreads();
    if (threadIdx.x == 0) g_is64 = !bad;
}

__global__ void zero_kernel() {
    int i = blockIdx.x * blockDim.x + threadIdx.x;
    if (i < NN) g_degcnt[i] = 0ull;
}

// fused xh_pack + pack_w (runs on aux stream, concurrent with edge chain)
#define XH_BLOCKS 6250
#define PW_BLOCKS 512
__global__ __launch_bounds__(256) void prep2_kernel(
        const float* __restrict__ X, const float* __restrict__ H,
        const float* __restrict__ wxi, const float* __restrict__ whi,
        const float* __restrict__ wxf, const float* __restrict__ whf,
        const float* __restrict__ wxc, const float* __restrict__ whc,
        const float* __restrict__ wxo, const float* __restrict__ who) {
    int b = blockIdx.x;
    int tid = threadIdx.x;
    if (b < XH_BLOCKS) {
        int gid = b * 256 + tid;
        if (gid >= NN * 32) return;
        int n = gid >> 5, lane = gid & 31;
        float4 a, c;
        if (lane < 16) {
            a = ((const float4*)X)[(size_t)n * 32 + lane * 2];
            c = ((const float4*)X)[(size_t)n * 32 + lane * 2 + 1];
        } else {
            int l = lane - 16;
            a = ((const float4*)H)[(size_t)n * 32 + l * 2];
            c = ((const float4*)H)[(size_t)n * 32 + l * 2 + 1];
        }
        uint4 o;
        o.x = h2_bits(__floats2half2_rn(a.x, a.y));
        o.y = h2_bits(__floats2half2_rn(a.z, a.w));
        o.z = h2_bits(__floats2half2_rn(c.x, c.y));
        o.w = h2_bits(__floats2half2_rn(c.z, c.w));
        ((uint4*)g_XH)[(size_t)n * 32 + lane] = o;
    } else {
        int idx = (b - XH_BLOCKS) * 256 + tid;
        int r = idx >> 9, c = idx & 511;   // r = k, c = n
        int g = c >> 7, cc = c & 127;
        const float* W;
        int rr;
        if (r < 128) {
            W = (g == 0) ? wxi : (g == 1) ? wxf : (g == 2) ? wxc : wxo;
            rr = r;
        } else {
            W = (g == 0) ? whi : (g == 1) ? whf : (g == 2) ? whc : who;
            rr = r - 128;
        }
        g_Wh[c * 256 + r] = __float2half(W[rr * 128 + cc]);
    }
}

// one packed 64-bit atomic per edge; old value's count = this edge's slot in row
__global__ void deg_kernel(const void* __restrict__ ei, const float* __restrict__ w) {
    int e = blockIdx.x * blockDim.x + threadIdx.x;
    if (e >= EE) return;
    int is64 = g_is64;
    int dst = edge_dst(ei, e, is64);
    unsigned fx = __float2uint_rn(w[e] * DEG_SCALE);
    unsigned long long old =
        atomicAdd(&g_degcnt[dst], (1ull << 40) + (unsigned long long)fx);
    g_slot[e] = (unsigned)(old >> 40);
}

// exclusive scan of counts -> g_rowoff, plus dis = rsqrt(deg) (merged pass)
__global__ void scan_kernel() {
    __shared__ int wsum[32];
    __shared__ int wpref[32];
    int tid = threadIdx.x, lane = tid & 31, wid = tid >> 5;
    int carry = 0;
    for (int base = 0; base < NN; base += 1024) {
        int i = base + tid;
        int v = 0;
        if (i < NN) {
            unsigned long long pc = g_degcnt[i];
            v = (int)(pc >> 40);
            float d = (float)(double)(pc & ((1ull << 40) - 1)) * (1.0f / DEG_SCALE);
            g_dis[i] = (d > 0.0f) ? rsqrtf(d) : 0.0f;
        }
        int x = v;
#pragma unroll
        for (int off = 1; off < 32; off <<= 1) {
            int t = __shfl_up_sync(0xffffffffu, x, off);
            if (lane >= off) x += t;
        }
        if (lane == 31) wsum[wid] = x;
        __syncthreads();
        if (wid == 0) {
            int y = wsum[lane];
#pragma unroll
            for (int off = 1; off < 32; off <<= 1) {
                int t = __shfl_up_sync(0xffffffffu, y, off);
                if (lane >= off) y += t;
            }
            wpref[lane] = y;
        }
        __syncthreads();
        int incl = x + ((wid > 0) ? wpref[wid - 1] : 0);
        if (i < NN) g_rowoff[i] = carry + incl - v;
        carry += wpref[31];
        __syncthreads();
    }
    if (tid == 0) g_rowoff[NN] = carry;
}

// no atomics: slot precomputed by deg_kernel
__global__ void build_kernel(const void* __restrict__ ei, const float* __restrict__ w) {
    int e = blockIdx.x * blockDim.x + threadIdx.x;
    if (e >= EE) return;
    int is64 = g_is64;
    int s = edge_src(ei, e, is64);
    int d = edge_dst(ei, e, is64);
    float nrm = g_dis[s] * w[e] * g_dis[d];
    int slot = g_rowoff[d] + (int)g_slot[e];
    g_edata[slot] = make_uint2((unsigned)s, __float_as_uint(nrm));
}

// ---------------- aggregation (fp16 gather, fp32 accum -> fp16 out) ------------
// processes rows [row_base, row_base + nrows)
__global__ __launch_bounds__(256) void agg_kernel(int row_base, int nrows) {
    int n = row_base + blockIdx.x * 8 + (threadIdx.x >> 5);
    if (n >= row_base + nrows || n >= NN) return;
    int lane = threadIdx.x & 31;
    int beg = g_rowoff[n];
    int end = g_rowoff[n + 1];
    const uint4* XH4 = (const uint4*)g_XH;

    float acc[8];
#pragma unroll
    for (int i = 0; i < 8; i++) acc[i] = 0.0f;

    int j = beg;
    for (; j + 1 < end; j += 2) {
        uint2 e0 = g_edata[j];
        uint2 e1 = g_edata[j + 1];
        uint4 v0 = XH4[(size_t)e0.x * 32 + lane];
        uint4 v1 = XH4[(size_t)e1.x * 32 + lane];
        float w0 = __uint_as_float(e0.y);
        float w1 = __uint_as_float(e1.y);
        const __half2* h0 = (const __half2*)&v0;
        const __half2* h1 = (const __half2*)&v1;
#pragma unroll
        for (int q = 0; q < 4; q++) {
            float2 f0 = __half22float2(h0[q]);
            float2 f1 = __half22float2(h1[q]);
            acc[q * 2 + 0] += f0.x * w0 + f1.x * w1;
            acc[q * 2 + 1] += f0.y * w0 + f1.y * w1;
        }
    }
    if (j < end) {
        uint2 e0 = g_edata[j];
        uint4 v0 = XH4[(size_t)e0.x * 32 + lane];
        float w0 = __uint_as_float(e0.y);
        const __half2* h0 = (const __half2*)&v0;
#pragma unroll
        for (int q = 0; q < 4; q++) {
            float2 f0 = __half22float2(h0[q]);
            acc[q * 2 + 0] += f0.x * w0;
            acc[q * 2 + 1] += f0.y * w0;
        }
    }

    uint4 o;
    o.x = h2_bits(__floats2half2_rn(acc[0], acc[1]));
    o.y = h2_bits(__floats2half2_rn(acc[2], acc[3]));
    o.z = h2_bits(__floats2half2_rn(acc[4], acc[5]));
    o.w = h2_bits(__floats2half2_rn(acc[6], acc[7]));
    ((uint4*)g_Gh)[(size_t)n * 32 + lane] = o;
}

// ---------------- fused fp16 GEMM + LSTM gates, cp.async + ldmatrix ------------
// Block: 128 rows x 32 channels x 4 gates; m0 = (m_base + blockIdx.x) * 128.
// __launch_bounds__(256,2): cap regs at 128 -> 2 resident blocks/SM.
__global__ __launch_bounds__(256, 2) void gemm_gate_kernel(
        int m_base,
        const float* __restrict__ C,
        const float* __restrict__ bxi, const float* __restrict__ bhi, const float* __restrict__ bi,
        const float* __restrict__ bxf, const float* __restrict__ bhf, const float* __restrict__ bf,
        const float* __restrict__ bxc, const float* __restrict__ bhc, const float* __restrict__ bc,
        const float* __restrict__ bxo, const float* __restrict__ bho, const float* __restrict__ bo,
        const float* __restrict__ wci, const float* __restrict__ wcf, const float* __restrict__ wco,
        float* __restrict__ out) {
    __shared__ __align__(16) char smem[44544];
    float (*sb)[128] = (float(*)[128])(smem + 40960);
    float (*swc)[128] = (float(*)[128])(smem + 43008);

    int m0 = (m_base + blockIdx.x) * 128;
    int c0 = blockIdx.y * 32;
    int tid = threadIdx.x;
    int warp = tid >> 5, lane = tid & 31;
    int wm = warp >> 2, wn = warp & 3;
    int g = lane >> 2, tg = lane & 3;

    if (tid < 128) {
        sb[0][tid] = bxi[tid] + bhi[tid] + bi[tid];
        sb[1][tid] = bxf[tid] + bhf[tid] + bf[tid];
        sb[2][tid] = bxc[tid] + bhc[tid] + bc[tid];
        sb[3][tid] = bxo[tid] + bho[tid] + bo[tid];
        swc[0][tid] = wci[tid];
        swc[1][tid] = wcf[tid];
        swc[2][tid] = wco[tid];
    }

    unsigned smem_base = (unsigned)__cvta_generic_to_shared(smem);

    // per-thread cp.async slots (2 x 16B for A, 2 x 16B for B)
    int aslot0 = tid * 2, aslot1 = tid * 2 + 1;
    int arow0 = aslot0 >> 2, ac0 = (aslot0 & 3) * 8;
    int arow1 = aslot1 >> 2, ac1 = (aslot1 & 3) * 8;
    int gr0 = m0 + arow0, gr1 = m0 + arow1;
    const __half* asrc0 = g_Gh + (size_t)(gr0 < NN ? gr0 : 0) * 256 + ac0;
    const __half* asrc1 = g_Gh + (size_t)(gr1 < NN ? gr1 : 0) * 256 + ac1;
    int bgi0 = aslot0 >> 7, brow0 = (aslot0 >> 2) & 31;
    int bgi1 = aslot1 >> 7, brow1 = (aslot1 >> 2) & 31;
    const __half* bsrc0 = g_Wh + (size_t)(bgi0 * 128 + c0 + brow0) * 256 + ac0;
    const __half* bsrc1 = g_Wh + (size_t)(bgi1 * 128 + c0 + brow1) * 256 + ac1;
    unsigned adst0 = smem_base + arow0 * 80 + ac0 * 2;
    unsigned adst1 = smem_base + arow1 * 80 + ac1 * 2;
    unsigned bdst0 = smem_base + 20480 + (bgi0 * 32 + brow0) * 80 + ac0 * 2;
    unsigned bdst1 = smem_base + 20480 + (bgi1 * 32 + brow1) * 80 + ac1 * 2;

#define ISSUE_TILE(kt, buf)                                                     \
    do {                                                                        \
        int koff = (kt) * 32;                                                   \
        unsigned bo_ = (buf) * 10240u;                                          \
        cpa16(adst0 + bo_, asrc0 + koff, gr0 < NN);                             \
        cpa16(adst1 + bo_, asrc1 + koff, gr1 < NN);                             \
        cpa16(bdst0 + bo_, bsrc0 + koff, 1);                                    \
        cpa16(bdst1 + bo_, bsrc1 + koff, 1);                                    \
        asm volatile("cp.async.commit_group;");                                 \
    } while (0)

    // ldmatrix per-lane address parts
    int a_lrow = lane & 15;
    int a_lcol = (lane >> 4) * 16;
    int b_lrow = lane & 7;
    int b_lcol = ((lane >> 3) & 1) * 16;

    float d[4][4][4];   // [mt][gate][elem]
#pragma unroll
    for (int mt = 0; mt < 4; ++mt)
#pragma unroll
        for (int gi = 0; gi < 4; ++gi)
#pragma unroll
            for (int i = 0; i < 4; ++i) d[mt][gi][i] = 0.0f;

    ISSUE_TILE(0, 0);

    for (int kt = 0; kt < 8; ++kt) {
        int cur = kt & 1;
        if (kt < 7) {
            ISSUE_TILE(kt + 1, cur ^ 1);
            asm volatile("cp.async.wait_group 1;");
        } else {
            asm volatile("cp.async.wait_group 0;");
        }
        __syncthreads();
        unsigned abase = smem_base + cur * 10240u;
        unsigned bbase = smem_base + 20480u + cur * 10240u;
#pragma unroll
        for (int ks = 0; ks < 2; ++ks) {
            int k0b = ks * 32;
            unsigned a[4][4];
#pragma unroll
            for (int mt = 0; mt < 4; ++mt) {
                int mb = wm * 64 + mt * 16;
                ldsm_x4(a[mt][0], a[mt][1], a[mt][2], a[mt][3],
                        abase + (mb + a_lrow) * 80 + k0b + a_lcol);
            }
            unsigned b[4][2];
#pragma unroll
            for (int gi = 0; gi < 4; ++gi) {
                ldsm_x2(b[gi][0], b[gi][1],
                        bbase + (gi * 32 + wn * 8 + b_lrow) * 80 + k0b + b_lcol);
            }
#pragma unroll
            for (int mt = 0; mt < 4; ++mt)
#pragma unroll
                for (int gi = 0; gi < 4; ++gi) {
                    asm volatile(
                        "mma.sync.aligned.m16n8k16.row.col.f32.f16.f16.f32 "
                        "{%0,%1,%2,%3}, {%4,%5,%6,%7}, {%8,%9}, {%0,%1,%2,%3};"
                        : "+f"(d[mt][gi][0]), "+f"(d[mt][gi][1]),
                          "+f"(d[mt][gi][2]), "+f"(d[mt][gi][3])
                        : "r"(a[mt][0]), "r"(a[mt][1]), "r"(a[mt][2]), "r"(a[mt][3]),
                          "r"(b[gi][0]), "r"(b[gi][1]));
                }
        }
        __syncthreads();
    }

    // epilogue
    int ch = c0 + wn * 8 + tg * 2;
    float sbi0 = sb[0][ch], sbi1 = sb[0][ch + 1];
    float sbf0 = sb[1][ch], sbf1 = sb[1][ch + 1];
    float sbc0 = sb[2][ch], sbc1 = sb[2][ch + 1];
    float sbo0 = sb[3][ch], sbo1 = sb[3][ch + 1];
    float wi0 = swc[0][ch], wi1 = swc[0][ch + 1];
    float wf0 = swc[1][ch], wf1 = swc[1][ch + 1];
    float wo0 = swc[2][ch], wo1 = swc[2][ch + 1];

#pragma unroll
    for (int mt = 0; mt < 4; ++mt) {
        int rbase = m0 + wm * 64 + mt * 16 + g;
#pragma unroll
        for (int hh = 0; hh < 2; ++hh) {
            int r = rbase + hh * 8;
            if (r >= NN) continue;
            int e = hh * 2;
            float2 Cv = *(const float2*)(C + (size_t)r * 128 + ch);
            float I0 = sigm(d[mt][0][e] + sbi0 + wi0 * Cv.x);
            float I1 = sigm(d[mt][0][e + 1] + sbi1 + wi1 * Cv.y);
            float F0 = sigm(d[mt][1][e] + sbf0 + wf0 * Cv.x);
            float F1 = sigm(d[mt][1][e + 1] + sbf1 + wf1 * Cv.y);
            float T0 = tanhf(d[mt][2][e] + sbc0);
            float T1 = tanhf(d[mt][2][e + 1] + sbc1);
            float Cn0 = F0 * Cv.x + I0 * T0;
            float Cn1 = F1 * Cv.y + I1 * T1;
            float O0 = sigm(d[mt][3][e] + sbo0 + wo0 * Cn0);
            float O1 = sigm(d[mt][3][e + 1] + sbo1 + wo1 * Cn1);
            float Hn0 = O0 * tanhf(Cn0);
            float Hn1 = O1 * tanhf(Cn1);
            *(float2*)(out + (size_t)r * 128 + ch) = make_float2(Hn0, Hn1);
            *(float2*)(out + (size_t)NN * 128 + (size_t)r * 128 + ch) = make_float2(Cn0, Cn1);
        }
    }
}

// ---------------- launch ----------------
extern "C" void kernel_launch(void* const* d_in, const int* in_sizes, int n_in,
                              void* d_out, int out_size) {
    (void)in_sizes; (void)n_in; (void)out_size;
    const float* X  = (const float*)d_in[0];
    const void*  EI = d_in[1];                 // int32 or int64 — detected on device
    const float* EW = (const float*)d_in[2];
    const float* H  = (const float*)d_in[3];
    const float* C  = (const float*)d_in[4];
    const float* Wx_i = (const float*)d_in[5];
    const float* bx_i = (const float*)d_in[6];
    const float* Wh_i = (const float*)d_in[7];
    const float* bh_i = (const float*)d_in[8];
    const float* Wx_f = (const float*)d_in[9];
    const float* bx_f = (const float*)d_in[10];
    const float* Wh_f = (const float*)d_in[11];
    const float* bh_f = (const float*)d_in[12];
    const float* Wx_c = (const float*)d_in[13];
    const float* bx_c = (const float*)d_in[14];
    const float* Wh_c = (const float*)d_in[15];
    const float* bh_c = (const float*)d_in[16];
    const float* Wx_o = (const float*)d_in[17];
    const float* bx_o = (const float*)d_in[18];
    const float* Wh_o = (const float*)d_in[19];
    const float* bh_o = (const float*)d_in[20];
    const float* wci  = (const float*)d_in[21];
    const float* wcf  = (const float*)d_in[22];
    const float* wco  = (const float*)d_in[23];
    const float* b_i  = (const float*)d_in[24];
    const float* b_f  = (const float*)d_in[25];
    const float* b_c  = (const float*)d_in[26];
    const float* b_o  = (const float*)d_in[27];
    float* out = (float*)d_out;

    static cudaStream_t s_aux = nullptr;
    static cudaEvent_t ev_fork = nullptr, ev_prep = nullptr, ev_done = nullptr;
    static cudaEvent_t ev_agg[4] = {nullptr, nullptr, nullptr, nullptr};
    if (s_aux == nullptr) {
        cudaStreamCreateWithFlags(&s_aux, cudaStreamNonBlocking);
        cudaEventCreateWithFlags(&ev_fork, cudaEventDisableTiming);
        cudaEventCreateWithFlags(&ev_prep, cudaEventDisableTiming);
        cudaEventCreateWithFlags(&ev_done, cudaEventDisableTiming);
        for (int i = 0; i < 4; i++) cudaEventCreateWithFlags(&ev_agg[i], cudaEventDisableTiming);
    }

    // fork: prep (XH/W packs) on aux, concurrent with edge-CSR chain on main
    cudaEventRecord(ev_fork, 0);
    cudaStreamWaitEvent(s_aux, ev_fork, 0);
    prep2_kernel<<<XH_BLOCKS + PW_BLOCKS, 256, 0, s_aux>>>(
        X, H, Wx_i, Wh_i, Wx_f, Wh_f, Wx_c, Wh_c, Wx_o, Wh_o);
    cudaEventRecord(ev_prep, s_aux);

    detect_kernel<<<1, 256>>>(EI);
    zero_kernel<<<(NN + 255) / 256, 256>>>();
    deg_kernel<<<(EE + 255) / 256, 256>>>(EI, EW);
    scan_kernel<<<1, 1024>>>();
    build_kernel<<<(EE + 255) / 256, 256>>>(EI, EW);

    // main needs XH (from prep2) before agg; gemm on aux is ordered after prep2
    cudaStreamWaitEvent(0, ev_prep, 0);

    // chunked agg (main) || gemm_gate (aux) pipeline over row blocks
    const int mb[5] = {0, 98, 196, 294, MB_TOTAL};
    for (int i = 0; i < 4; i++) {
        int row_base = mb[i] * 128;
        int row_end = mb[i + 1] * 128;
        if (row_end > NN) row_end = NN;
        int nrows = row_end - row_base;
        agg_kernel<<<(nrows + 7) / 8, 256>>>(row_base, nrows);
        cudaEventRecord(ev_agg[i], 0);
        cudaStreamWaitEvent(s_aux, ev_agg[i], 0);
        dim3 gg(mb[i + 1] - mb[i], 4);
        gemm_gate_kernel<<<gg, 256, 0, s_aux>>>(mb[i], C,
                                                bx_i, bh_i, b_i,
                                                bx_f, bh_f, b_f,
                                                bx_c, bh_c, b_c,
                                                bx_o, bh_o, b_o,
                                                wci, wcf, wco, out);
    }

    // join aux back into main before capture ends
    cudaEventRecord(ev_done, s_aux);
    cudaStreamWaitEvent(0, ev_done, 0);
}

// round 15
// speedup vs baseline: 1.1279x; 1.1279x over previous
#include <cuda_runtime.h>
#include <cuda_fp16.h>
#include <math.h>
#include <string.h>

#define NN 50000
#define EE 1600000
#define DEG_SCALE 67108864.0f          /* 2^26 fixed-point for packed deg */

// ---------------- scratch (static device arrays; no allocation) ----------------
static __device__ __align__(16) __half g_XH[(size_t)NN * 256];  // [N, X(128)|H(128)] fp16
static __device__ __align__(16) __half g_Gh[(size_t)NN * 256];  // [N,256] agg result, fp16
static __device__ __align__(16) __half g_Wh[512 * 256];  // W_cat^T: [n=512][k=256] fp16
static __device__ unsigned long long g_degcnt[NN];  // low40: deg fixed-point, high: cnt
static __device__ float g_dis[NN];
static __device__ unsigned g_slot[EE];           // per-edge slot within its dst row
static __device__ int   g_rowoff[NN + 1];
static __device__ uint2 g_edata[EE];             // (src, bitcast(norm)) CSR-permuted
static __device__ int   g_is64;                  // 1 if edge_index really is int64

// ---------------- small helpers ----------------
__device__ __forceinline__ float sigm(float x) { return 1.0f / (1.0f + expf(-x)); }

__device__ __forceinline__ unsigned h2_bits(__half2 h) {
    unsigned u;
    memcpy(&u, &h, sizeof(u));
    return u;
}

__device__ __forceinline__ int edge_src(const void* ei, int e, int is64) {
    if (is64) return (int)((const long long*)ei)[e];
    return ((const int*)ei)[e];
}
__device__ __forceinline__ int edge_dst(const void* ei, int e, int is64) {
    if (is64) return (int)((const long long*)ei)[(size_t)EE + e];
    return ((const int*)ei)[(size_t)EE + e];
}

// cp.async 16B with zero-fill when pred==0
__device__ __forceinline__ void cpa16(unsigned smem, const void* g, int pred) {
    asm volatile("cp.async.ca.shared.global [%0], [%1], 16, %2;"
                 :: "r"(smem), "l"(g), "r"(pred ? 16 : 0));
}

__device__ __forceinline__ void ldsm_x4(unsigned& r0, unsigned& r1, unsigned& r2,
                                        unsigned& r3, unsigned addr) {
    asm volatile("ldmatrix.sync.aligned.m8n8.x4.shared.b16 {%0,%1,%2,%3}, [%4];"
                 : "=r"(r0), "=r"(r1), "=r"(r2), "=r"(r3) : "r"(addr));
}
__device__ __forceinline__ void ldsm_x2(unsigned& r0, unsigned& r1, unsigned addr) {
    asm volatile("ldmatrix.sync.aligned.m8n8.x2.shared.b16 {%0,%1}, [%2];"
                 : "=r"(r0), "=r"(r1) : "r"(addr));
}

// ---------------- preprocessing kernels ----------------
__global__ void detect_kernel(const void* ei) {
    __shared__ int bad;
    if (threadIdx.x == 0) bad = 0;
    __syncthreads();
    long long v = ((const long long*)ei)[threadIdx.x];
    if (v < 0 || v >= NN) bad = 1;   // benign race, any writer sets 1
    __syncthreads();
    if (threadIdx.x == 0) g_is64 = !bad;
}

__global__ void zero_kernel() {
    int i = blockIdx.x * blockDim.x + threadIdx.x;
    if (i < NN) g_degcnt[i] = 0ull;
}

// fused xh_pack + pack_w (runs on aux stream, concurrent with edge chain)
#define XH_BLOCKS 6250
#define PW_BLOCKS 512
__global__ __launch_bounds__(256) void prep2_kernel(
        const float* __restrict__ X, const float* __restrict__ H,
        const float* __restrict__ wxi, const float* __restrict__ whi,
        const float* __restrict__ wxf, const float* __restrict__ whf,
        const float* __restrict__ wxc, const float* __restrict__ whc,
        const float* __restrict__ wxo, const float* __restrict__ who) {
    int b = blockIdx.x;
    int tid = threadIdx.x;
    if (b < XH_BLOCKS) {
        int gid = b * 256 + tid;
        if (gid >= NN * 32) return;
        int n = gid >> 5, lane = gid & 31;
        float4 a, c;
        if (lane < 16) {
            a = ((const float4*)X)[(size_t)n * 32 + lane * 2];
            c = ((const float4*)X)[(size_t)n * 32 + lane * 2 + 1];
        } else {
            int l = lane - 16;
            a = ((const float4*)H)[(size_t)n * 32 + l * 2];
            c = ((const float4*)H)[(size_t)n * 32 + l * 2 + 1];
        }
        uint4 o;
        o.x = h2_bits(__floats2half2_rn(a.x, a.y));
        o.y = h2_bits(__floats2half2_rn(a.z, a.w));
        o.z = h2_bits(__floats2half2_rn(c.x, c.y));
        o.w = h2_bits(__floats2half2_rn(c.z, c.w));
        ((uint4*)g_XH)[(size_t)n * 32 + lane] = o;
    } else {
        int idx = (b - XH_BLOCKS) * 256 + tid;
        int r = idx >> 9, c = idx & 511;   // r = k, c = n
        int g = c >> 7, cc = c & 127;
        const float* W;
        int rr;
        if (r < 128) {
            W = (g == 0) ? wxi : (g == 1) ? wxf : (g == 2) ? wxc : wxo;
            rr = r;
        } else {
            W = (g == 0) ? whi : (g == 1) ? whf : (g == 2) ? whc : who;
            rr = r - 128;
        }
        g_Wh[c * 256 + r] = __float2half(W[rr * 128 + cc]);
    }
}

// one packed 64-bit atomic per edge; old value's count = this edge's slot in row
__global__ void deg_kernel(const void* __restrict__ ei, const float* __restrict__ w) {
    int e = blockIdx.x * blockDim.x + threadIdx.x;
    if (e >= EE) return;
    int is64 = g_is64;
    int dst = edge_dst(ei, e, is64);
    unsigned fx = __float2uint_rn(w[e] * DEG_SCALE);
    unsigned long long old =
        atomicAdd(&g_degcnt[dst], (1ull << 40) + (unsigned long long)fx);
    g_slot[e] = (unsigned)(old >> 40);
}

// exclusive scan of counts -> g_rowoff, plus dis = rsqrt(deg) (merged pass)
__global__ void scan_kernel() {
    __shared__ int wsum[32];
    __shared__ int wpref[32];
    int tid = threadIdx.x, lane = tid & 31, wid = tid >> 5;
    int carry = 0;
    for (int base = 0; base < NN; base += 1024) {
        int i = base + tid;
        int v = 0;
        if (i < NN) {
            unsigned long long pc = g_degcnt[i];
            v = (int)(pc >> 40);
            float d = (float)(double)(pc & ((1ull << 40) - 1)) * (1.0f / DEG_SCALE);
            g_dis[i] = (d > 0.0f) ? rsqrtf(d) : 0.0f;
        }
        int x = v;
#pragma unroll
        for (int off = 1; off < 32; off <<= 1) {
            int t = __shfl_up_sync(0xffffffffu, x, off);
            if (lane >= off) x += t;
        }
        if (lane == 31) wsum[wid] = x;
        __syncthreads();
        if (wid == 0) {
            int y = wsum[lane];
#pragma unroll
            for (int off = 1; off < 32; off <<= 1) {
                int t = __shfl_up_sync(0xffffffffu, y, off);
                if (lane >= off) y += t;
            }
            wpref[lane] = y;
        }
        __syncthreads();
        int incl = x + ((wid > 0) ? wpref[wid - 1] : 0);
        if (i < NN) g_rowoff[i] = carry + incl - v;
        carry += wpref[31];
        __syncthreads();
    }
    if (tid == 0) g_rowoff[NN] = carry;
}

// no atomics: slot precomputed by deg_kernel
__global__ void build_kernel(const void* __restrict__ ei, const float* __restrict__ w) {
    int e = blockIdx.x * blockDim.x + threadIdx.x;
    if (e >= EE) return;
    int is64 = g_is64;
    int s = edge_src(ei, e, is64);
    int d = edge_dst(ei, e, is64);
    float nrm = g_dis[s] * w[e] * g_dis[d];
    int slot = g_rowoff[d] + (int)g_slot[e];
    g_edata[slot] = make_uint2((unsigned)s, __float_as_uint(nrm));
}

// ---------------- aggregation (fp16 gather, fp32 accum -> fp16 out) ------------
__global__ __launch_bounds__(256) void agg_kernel() {
    int n = blockIdx.x * 8 + (threadIdx.x >> 5);
    if (n >= NN) return;
    int lane = threadIdx.x & 31;
    int beg = g_rowoff[n];
    int end = g_rowoff[n + 1];
    const uint4* XH4 = (const uint4*)g_XH;

    float acc[8];
#pragma unroll
    for (int i = 0; i < 8; i++) acc[i] = 0.0f;

    int j = beg;
    for (; j + 1 < end; j += 2) {
        uint2 e0 = g_edata[j];
        uint2 e1 = g_edata[j + 1];
        uint4 v0 = XH4[(size_t)e0.x * 32 + lane];
        uint4 v1 = XH4[(size_t)e1.x * 32 + lane];
        float w0 = __uint_as_float(e0.y);
        float w1 = __uint_as_float(e1.y);
        const __half2* h0 = (const __half2*)&v0;
        const __half2* h1 = (const __half2*)&v1;
#pragma unroll
        for (int q = 0; q < 4; q++) {
            float2 f0 = __half22float2(h0[q]);
            float2 f1 = __half22float2(h1[q]);
            acc[q * 2 + 0] += f0.x * w0 + f1.x * w1;
            acc[q * 2 + 1] += f0.y * w0 + f1.y * w1;
        }
    }
    if (j < end) {
        uint2 e0 = g_edata[j];
        uint4 v0 = XH4[(size_t)e0.x * 32 + lane];
        float w0 = __uint_as_float(e0.y);
        const __half2* h0 = (const __half2*)&v0;
#pragma unroll
        for (int q = 0; q < 4; q++) {
            float2 f0 = __half22float2(h0[q]);
            acc[q * 2 + 0] += f0.x * w0;
            acc[q * 2 + 1] += f0.y * w0;
        }
    }

    uint4 o;
    o.x = h2_bits(__floats2half2_rn(acc[0], acc[1]));
    o.y = h2_bits(__floats2half2_rn(acc[2], acc[3]));
    o.z = h2_bits(__floats2half2_rn(acc[4], acc[5]));
    o.w = h2_bits(__floats2half2_rn(acc[6], acc[7]));
    ((uint4*)g_Gh)[(size_t)n * 32 + lane] = o;
}

// ---------------- fused fp16 GEMM + LSTM gates, 64-row tile --------------------
// Block: 64 rows x 32 channels x 4 gates. 8 warps (wm 0-1 x wn 0-3), warp = 32
// rows x 8 ch x 4 gates -> 32 accum regs/thread, ~85 regs total -> 3 blocks/SM.
// smem: As[2] @0 (2*5120), Bs[2] @10240 (2*10240), sb @30720, swc @32768
__global__ __launch_bounds__(256) void gemm_gate_kernel(
        const float* __restrict__ C,
        const float* __restrict__ bxi, const float* __restrict__ bhi, const float* __restrict__ bi,
        const float* __restrict__ bxf, const float* __restrict__ bhf, const float* __restrict__ bf,
        const float* __restrict__ bxc, const float* __restrict__ bhc, const float* __restrict__ bc,
        const float* __restrict__ bxo, const float* __restrict__ bho, const float* __restrict__ bo,
        const float* __restrict__ wci, const float* __restrict__ wcf, const float* __restrict__ wco,
        float* __restrict__ out) {
    __shared__ __align__(16) char smem[34304];
    float (*sb)[128] = (float(*)[128])(smem + 30720);
    float (*swc)[128] = (float(*)[128])(smem + 32768);

    int m0 = blockIdx.x * 64;
    int c0 = blockIdx.y * 32;
    int tid = threadIdx.x;
    int warp = tid >> 5, lane = tid & 31;
    int wm = warp >> 2, wn = warp & 3;
    int g = lane >> 2, tg = lane & 3;

    if (tid < 128) {
        sb[0][tid] = bxi[tid] + bhi[tid] + bi[tid];
        sb[1][tid] = bxf[tid] + bhf[tid] + bf[tid];
        sb[2][tid] = bxc[tid] + bhc[tid] + bc[tid];
        sb[3][tid] = bxo[tid] + bho[tid] + bo[tid];
        swc[0][tid] = wci[tid];
        swc[1][tid] = wcf[tid];
        swc[2][tid] = wco[tid];
    }

    unsigned smem_base = (unsigned)__cvta_generic_to_shared(smem);

    // A: 64 rows x 4 x 16B slots = 256 -> 1 per thread
    int arow = tid >> 2, ac = (tid & 3) * 8;
    int gr = m0 + arow;
    const __half* asrc = g_Gh + (size_t)(gr < NN ? gr : 0) * 256 + ac;
    unsigned adst = smem_base + arow * 80 + ac * 2;
    // B: 4 gates x 32 rows x 4 slots = 512 -> 2 per thread
    int bslot0 = tid * 2, bslot1 = tid * 2 + 1;
    int bgi0 = bslot0 >> 7, brow0 = (bslot0 >> 2) & 31, bc0 = (bslot0 & 3) * 8;
    int bgi1 = bslot1 >> 7, brow1 = (bslot1 >> 2) & 31, bc1 = (bslot1 & 3) * 8;
    const __half* bsrc0 = g_Wh + (size_t)(bgi0 * 128 + c0 + brow0) * 256 + bc0;
    const __half* bsrc1 = g_Wh + (size_t)(bgi1 * 128 + c0 + brow1) * 256 + bc1;
    unsigned bdst0 = smem_base + 10240 + (bgi0 * 32 + brow0) * 80 + bc0 * 2;
    unsigned bdst1 = smem_base + 10240 + (bgi1 * 32 + brow1) * 80 + bc1 * 2;

#define ISSUE_TILE(kt, buf)                                                     \
    do {                                                                        \
        int koff = (kt) * 32;                                                   \
        cpa16(adst + (buf) * 5120u, asrc + koff, gr < NN);                      \
        cpa16(bdst0 + (buf) * 10240u, bsrc0 + koff, 1);                         \
        cpa16(bdst1 + (buf) * 10240u, bsrc1 + koff, 1);                         \
        asm volatile("cp.async.commit_group;");                                 \
    } while (0)

    // ldmatrix per-lane address parts
    int a_lrow = lane & 15;
    int a_lcol = (lane >> 4) * 16;
    int b_lrow = lane & 7;
    int b_lcol = ((lane >> 3) & 1) * 16;

    float d[2][4][4];   // [mt][gate][elem]
#pragma unroll
    for (int mt = 0; mt < 2; ++mt)
#pragma unroll
        for (int gi = 0; gi < 4; ++gi)
#pragma unroll
            for (int i = 0; i < 4; ++i) d[mt][gi][i] = 0.0f;

    ISSUE_TILE(0, 0);

    for (int kt = 0; kt < 8; ++kt) {
        int cur = kt & 1;
        if (kt < 7) {
            ISSUE_TILE(kt + 1, cur ^ 1);
            asm volatile("cp.async.wait_group 1;");
        } else {
            asm volatile("cp.async.wait_group 0;");
        }
        __syncthreads();
        unsigned abase = smem_base + cur * 5120u;
        unsigned bbase = smem_base + 10240u + cur * 10240u;
#pragma unroll
        for (int ks = 0; ks < 2; ++ks) {
            int k0b = ks * 32;
            unsigned a[2][4];
#pragma unroll
            for (int mt = 0; mt < 2; ++mt) {
                int mb = wm * 32 + mt * 16;
                ldsm_x4(a[mt][0], a[mt][1], a[mt][2], a[mt][3],
                        abase + (mb + a_lrow) * 80 + k0b + a_lcol);
            }
            unsigned b[4][2];
#pragma unroll
            for (int gi = 0; gi < 4; ++gi) {
                ldsm_x2(b[gi][0], b[gi][1],
                        bbase + (gi * 32 + wn * 8 + b_lrow) * 80 + k0b + b_lcol);
            }
#pragma unroll
            for (int mt = 0; mt < 2; ++mt)
#pragma unroll
                for (int gi = 0; gi < 4; ++gi) {
                    asm volatile(
                        "mma.sync.aligned.m16n8k16.row.col.f32.f16.f16.f32 "
                        "{%0,%1,%2,%3}, {%4,%5,%6,%7}, {%8,%9}, {%0,%1,%2,%3};"
                        : "+f"(d[mt][gi][0]), "+f"(d[mt][gi][1]),
                          "+f"(d[mt][gi][2]), "+f"(d[mt][gi][3])
                        : "r"(a[mt][0]), "r"(a[mt][1]), "r"(a[mt][2]), "r"(a[mt][3]),
                          "r"(b[gi][0]), "r"(b[gi][1]));
                }
        }
        __syncthreads();
    }

    // epilogue: thread owns channels ch, ch+1 for rows rbase, rbase+8 per mt
    int ch = c0 + wn * 8 + tg * 2;
    float sbi0 = sb[0][ch], sbi1 = sb[0][ch + 1];
    float sbf0 = sb[1][ch], sbf1 = sb[1][ch + 1];
    float sbc0 = sb[2][ch], sbc1 = sb[2][ch + 1];
    float sbo0 = sb[3][ch], sbo1 = sb[3][ch + 1];
    float wi0 = swc[0][ch], wi1 = swc[0][ch + 1];
    float wf0 = swc[1][ch], wf1 = swc[1][ch + 1];
    float wo0 = swc[2][ch], wo1 = swc[2][ch + 1];

#pragma unroll
    for (int mt = 0; mt < 2; ++mt) {
        int rbase = m0 + wm * 32 + mt * 16 + g;
#pragma unroll
        for (int hh = 0; hh < 2; ++hh) {
            int r = rbase + hh * 8;
            if (r >= NN) continue;
            int e = hh * 2;
            float2 Cv = *(const float2*)(C + (size_t)r * 128 + ch);
            float I0 = sigm(d[mt][0][e] + sbi0 + wi0 * Cv.x);
            float I1 = sigm(d[mt][0][e + 1] + sbi1 + wi1 * Cv.y);
            float F0 = sigm(d[mt][1][e] + sbf0 + wf0 * Cv.x);
            float F1 = sigm(d[mt][1][e + 1] + sbf1 + wf1 * Cv.y);
            float T0 = tanhf(d[mt][2][e] + sbc0);
            float T1 = tanhf(d[mt][2][e + 1] + sbc1);
            float Cn0 = F0 * Cv.x + I0 * T0;
            float Cn1 = F1 * Cv.y + I1 * T1;
            float O0 = sigm(d[mt][3][e] + sbo0 + wo0 * Cn0);
            float O1 = sigm(d[mt][3][e + 1] + sbo1 + wo1 * Cn1);
            float Hn0 = O0 * tanhf(Cn0);
            float Hn1 = O1 * tanhf(Cn1);
            *(float2*)(out + (size_t)r * 128 + ch) = make_float2(Hn0, Hn1);
            *(float2*)(out + (size_t)NN * 128 + (size_t)r * 128 + ch) = make_float2(Cn0, Cn1);
        }
    }
}

// ---------------- launch ----------------
extern "C" void kernel_launch(void* const* d_in, const int* in_sizes, int n_in,
                              void* d_out, int out_size) {
    (void)in_sizes; (void)n_in; (void)out_size;
    const float* X  = (const float*)d_in[0];
    const void*  EI = d_in[1];                 // int32 or int64 — detected on device
    const float* EW = (const float*)d_in[2];
    const float* H  = (const float*)d_in[3];
    const float* C  = (const float*)d_in[4];
    const float* Wx_i = (const float*)d_in[5];
    const float* bx_i = (const float*)d_in[6];
    const float* Wh_i = (const float*)d_in[7];
    const float* bh_i = (const float*)d_in[8];
    const float* Wx_f = (const float*)d_in[9];
    const float* bx_f = (const float*)d_in[10];
    const float* Wh_f = (const float*)d_in[11];
    const float* bh_f = (const float*)d_in[12];
    const float* Wx_c = (const float*)d_in[13];
    const float* bx_c = (const float*)d_in[14];
    const float* Wh_c = (const float*)d_in[15];
    const float* bh_c = (const float*)d_in[16];
    const float* Wx_o = (const float*)d_in[17];
    const float* bx_o = (const float*)d_in[18];
    const float* Wh_o = (const float*)d_in[19];
    const float* bh_o = (const float*)d_in[20];
    const float* wci  = (const float*)d_in[21];
    const float* wcf  = (const float*)d_in[22];
    const float* wco  = (const float*)d_in[23];
    const float* b_i  = (const float*)d_in[24];
    const float* b_f  = (const float*)d_in[25];
    const float* b_c  = (const float*)d_in[26];
    const float* b_o  = (const float*)d_in[27];
    float* out = (float*)d_out;

    static cudaStream_t s_aux = nullptr;
    static cudaEvent_t ev_fork = nullptr, ev_join = nullptr;
    if (s_aux == nullptr) {
        cudaStreamCreateWithFlags(&s_aux, cudaStreamNonBlocking);
        cudaEventCreateWithFlags(&ev_fork, cudaEventDisableTiming);
        cudaEventCreateWithFlags(&ev_join, cudaEventDisableTiming);
    }

    // fork: prep (XH/W packs) runs concurrent with the edge-CSR chain
    cudaEventRecord(ev_fork, 0);
    cudaStreamWaitEvent(s_aux, ev_fork, 0);
    prep2_kernel<<<XH_BLOCKS + PW_BLOCKS, 256, 0, s_aux>>>(
        X, H, Wx_i, Wh_i, Wx_f, Wh_f, Wx_c, Wh_c, Wx_o, Wh_o);
    cudaEventRecord(ev_join, s_aux);

    detect_kernel<<<1, 256>>>(EI);
    zero_kernel<<<(NN + 255) / 256, 256>>>();
    deg_kernel<<<(EE + 255) / 256, 256>>>(EI, EW);
    scan_kernel<<<1, 1024>>>();
    build_kernel<<<(EE + 255) / 256, 256>>>(EI, EW);

    // join: agg needs XH (aux) + edata (main)
    cudaStreamWaitEvent(0, ev_join, 0);
    agg_kernel<<<(NN + 7) / 8, 256>>>();
    dim3 gg((NN + 63) / 64, 4);
    gemm_gate_kernel<<<gg, 256>>>(C,
                                  bx_i, bh_i, b_i,
                                  bx_f, bh_f, b_f,
                                  bx_c, bh_c, b_c,
                                  bx_o, bh_o, b_o,
                                  wci, wcf, wco, out);
}